// round 11
// baseline (speedup 1.0000x reference)
#include <cuda_runtime.h>
#include <math_constants.h>

// Per-(batch,cell) sums: index == blockIdx.x. Zero-init at module load.
__device__ float g_cells[128 * 4 * 4];
__device__ unsigned int g_done = 0;   // ticket counter; reset by last block

// ---------------------------------------------------------------------------
// Fused kernel: 2048 blocks x 256 threads, one block per (batch, grid cell).
// Phase 1 (all blocks): privately sum own 128x128 cell -> g_cells[bid].
// Phase 2 (last block, threadfence-reduction pattern): threads 0..127 each
// run window-sum + argmax for one batch, write float (row, col).
// Mean's /16384 scale skipped: uniform positive factor, argmax-invariant.
// NOTE: plain LDG (no __ldcs) — round-10 post-mortem attributed a 15%
// bandwidth loss to the evict-first hint on this single-touch stream.
// ---------------------------------------------------------------------------
__global__ __launch_bounds__(256) void region_selector_fused(
    const float* __restrict__ x, float* __restrict__ out)
{
    const int bid   = blockIdx.x;      // batch*16 + gr*4 + gc
    const int batch = bid >> 4;
    const int cell  = bid & 15;
    const int gr    = cell >> 2;
    const int gc    = cell & 3;

    const int t  = threadIdx.x;        // 0..255
    const int c4 = t & 31;             // float4 col within 128-float cell row
    const int r0 = t >> 5;             // 0..7, rows r0 + 8i

    const float4* __restrict__ p =
        reinterpret_cast<const float4*>(x) + (size_t)batch * 65536;
    const int cellbase = gr * (128 * 128) + gc * 32;   // float4 units

    float s = 0.0f;
    #pragma unroll
    for (int i = 0; i < 16; i++) {
        const float4 v = p[cellbase + (r0 + 8 * i) * 128 + c4];
        s += (v.x + v.y) + (v.z + v.w);
    }

    #pragma unroll
    for (int o = 16; o > 0; o >>= 1)
        s += __shfl_xor_sync(0xffffffffu, s, o);

    __shared__ float ws[8];
    __shared__ bool  is_last;
    if ((t & 31) == 0) ws[t >> 5] = s;
    __syncthreads();

    if (t == 0) {
        const float tot = (ws[0] + ws[1]) + (ws[2] + ws[3])
                        + (ws[4] + ws[5]) + (ws[6] + ws[7]);
        g_cells[bid] = tot;
        __threadfence();                       // publish before ticket bump
        const unsigned int ticket = atomicAdd(&g_done, 1u);
        is_last = (ticket == gridDim.x - 1);   // all g_cells now visible
    }
    __syncthreads();

    if (is_last) {
        if (t < 128) {
            const int b = t;                   // one batch per thread
            float cells[16];
            #pragma unroll
            for (int i = 0; i < 16; i++) cells[i] = g_cells[b * 16 + i];

            float best = -CUDART_INF_F;
            int   bi   = 0;
            #pragma unroll
            for (int r = 0; r < 2; r++) {
                #pragma unroll
                for (int c = 0; c < 2; c++) {
                    float w = 0.0f;
                    #pragma unroll
                    for (int dr = 0; dr < 3; dr++)
                        #pragma unroll
                        for (int dc = 0; dc < 3; dc++)
                            w += cells[(r + dr) * 4 + (c + dc)];
                    if (w > best) { best = w; bi = r * 2 + c; }  // first-hit
                }
            }
            out[b * 2 + 0] = (float)(bi >> 1);  // row (float output dtype)
            out[b * 2 + 1] = (float)(bi & 1);   // col
        }
        if (t == 0) g_done = 0;                // reset for next graph replay
    }
}

extern "C" void kernel_launch(void* const* d_in, const int* in_sizes, int n_in,
                              void* d_out, int out_size) {
    const float* x = (const float*)d_in[0];
    float* out = (float*)d_out;
    region_selector_fused<<<2048, 256>>>(x, out);
}

// round 12
// speedup vs baseline: 1.0637x; 1.0637x over previous
#include <cuda_runtime.h>
#include <math_constants.h>

// Per-(batch, cell, half) sums: index == blockIdx.x. Zero-init at load.
__device__ float g_half[128 * 16 * 2];
__device__ unsigned int g_done = 0;   // ticket; reset by last block each run

// ---------------------------------------------------------------------------
// Fused kernel: 4096 blocks x 256 threads, one block per 64-row half-cell
// (32 KB contiguous-in-cell work unit -> 3.46 waves, smooth tail).
// Phase 1: privately sum own 64x128 half-cell -> g_half[bid]  (__ldcs:
// evict-first confirmed faster on this single-touch stream, R10 vs R11).
// Phase 2 (last block, threadfence-reduction): threads 0..127 combine the
// 32 half-sums of their batch into 16 cells, window-sum + argmax, write
// float (row, col). Mean /16384 skipped: uniform positive, argmax-safe.
// ---------------------------------------------------------------------------
__global__ __launch_bounds__(256) void region_selector_fused(
    const float* __restrict__ x, float* __restrict__ out)
{
    const int bid   = blockIdx.x;      // batch*32 + cell*2 + half
    const int batch = bid >> 5;
    const int rem   = bid & 31;
    const int cell  = rem >> 1;        // 0..15
    const int half  = rem & 1;         // 64-row half within cell
    const int gr    = cell >> 2;
    const int gc    = cell & 3;

    const int t  = threadIdx.x;        // 0..255
    const int c4 = t & 31;             // float4 col within 128-float cell row
    const int r0 = t >> 5;             // 0..7; rows half*64 + r0 + 8i, i<8

    const float4* __restrict__ p =
        reinterpret_cast<const float4*>(x) + (size_t)batch * 65536;
    const int base = gr * (128 * 128) + gc * 32 + half * (64 * 128); // f4 units

    float s = 0.0f;
    #pragma unroll
    for (int i = 0; i < 8; i++) {
        const float4 v = __ldcs(&p[base + (r0 + 8 * i) * 128 + c4]);
        s += (v.x + v.y) + (v.z + v.w);
    }

    #pragma unroll
    for (int o = 16; o > 0; o >>= 1)
        s += __shfl_xor_sync(0xffffffffu, s, o);

    __shared__ float ws[8];
    __shared__ bool  is_last;
    if ((t & 31) == 0) ws[t >> 5] = s;
    __syncthreads();

    if (t == 0) {
        g_half[bid] = (ws[0] + ws[1]) + (ws[2] + ws[3])
                    + (ws[4] + ws[5]) + (ws[6] + ws[7]);
        __threadfence();                       // publish before ticket bump
        const unsigned int ticket = atomicAdd(&g_done, 1u);
        is_last = (ticket == gridDim.x - 1);   // all g_half now visible
    }
    __syncthreads();

    if (is_last) {
        if (t < 128) {
            const int b = t;                   // one batch per thread
            float cells[16];
            #pragma unroll
            for (int i = 0; i < 16; i++)
                cells[i] = g_half[b * 32 + 2 * i] + g_half[b * 32 + 2 * i + 1];

            float best = -CUDART_INF_F;
            int   bi   = 0;
            #pragma unroll
            for (int r = 0; r < 2; r++) {
                #pragma unroll
                for (int c = 0; c < 2; c++) {
                    float w = 0.0f;
                    #pragma unroll
                    for (int dr = 0; dr < 3; dr++)
                        #pragma unroll
                        for (int dc = 0; dc < 3; dc++)
                            w += cells[(r + dr) * 4 + (c + dc)];
                    if (w > best) { best = w; bi = r * 2 + c; }  // first-hit
                }
            }
            out[b * 2 + 0] = (float)(bi >> 1);  // row (float output dtype)
            out[b * 2 + 1] = (float)(bi & 1);   // col
        }
        if (t == 0) g_done = 0;                // reset for next graph replay
    }
}

extern "C" void kernel_launch(void* const* d_in, const int* in_sizes, int n_in,
                              void* d_out, int out_size) {
    const float* x = (const float*)d_in[0];
    float* out = (float*)d_out;
    region_selector_fused<<<4096, 256>>>(x, out);
}